// round 1
// baseline (speedup 1.0000x reference)
#include <cuda_runtime.h>
#include <math.h>

// Forest-Ruth / Yoshida 4th-order symplectic coefficients (compile-time doubles,
// folded to float constants).
#define C13   1.2599210498948731647672106072782  // 2^(1/3)
#define DEN   (2.0 - C13)
#define C0d   (0.5 / DEN)
#define C1d   ((0.5 - 0.62996052494743658238360530363911) / DEN)   // 0.5 - 2^(-2/3)
#define D0d   (1.0 / DEN)
#define D1d   (-C13 / DEN)
// C_COEF = (C0, C1, C1, C0) ; D_COEF = (D0, D1, D0, 0)

__global__ __launch_bounds__(256)
void ode_kernel(const float* __restrict__ p0,
                const float* __restrict__ q0,
                const float* __restrict__ t0p,
                const float* __restrict__ t1p,
                float* __restrict__ out_p,
                float* __restrict__ out_q,
                int n)
{
    int i = blockIdx.x * blockDim.x + threadIdx.x;
    if (i >= n) return;

    const float dt = *t1p - *t0p;
    // reference: n_steps = round(|dt| / (EPS*4)) with EPS=0.01 -> |dt| * 25
    const int n_steps = (int)rintf(fabsf(dt) * 25.0f);

    float kp = p0[i];
    float kq = q0[i];

    if (n_steps > 0) {
        const float h   = dt / (float)n_steps;
        const float ch0 = (float)C0d * h;
        const float ch1 = (float)C1d * h;
        const float dh0 = (float)D0d * h;
        const float dh1 = (float)D1d * h;

        for (int s = 0; s < n_steps; ++s) {
            // substep 0: c=C0, d=D0
            kq = fmaf(ch0, kp, kq);
            kp = fmaf(-dh0, __sinf(kq), kp);
            // substep 1: c=C1, d=D1
            kq = fmaf(ch1, kp, kq);
            kp = fmaf(-dh1, __sinf(kq), kp);
            // substep 2: c=C1, d=D0
            kq = fmaf(ch1, kp, kq);
            kp = fmaf(-dh0, __sinf(kq), kp);
            // substep 3: c=C0, d=0 -> pure drift
            kq = fmaf(ch0, kp, kq);
        }
    }

    out_p[i] = kp;
    out_q[i] = kq;
}

extern "C" void kernel_launch(void* const* d_in, const int* in_sizes, int n_in,
                              void* d_out, int out_size)
{
    const float* p0 = (const float*)d_in[0];
    const float* q0 = (const float*)d_in[1];
    const float* t0 = (const float*)d_in[2];
    const float* t1 = (const float*)d_in[3];

    const int n = in_sizes[0];            // B*N = 4*1048576
    float* out_p = (float*)d_out;         // outputs concatenated: (kp, kq)
    float* out_q = (float*)d_out + n;

    const int threads = 256;
    const int blocks  = (n + threads - 1) / threads;
    ode_kernel<<<blocks, threads>>>(p0, q0, t0, t1, out_p, out_q, n);
}